// round 15
// baseline (speedup 1.0000x reference)
#include <cuda_runtime.h>

#define NB   8
#define NHH  8
#define LL   1024
#define NSPLIT 4
// sqrt(8) * log2(e): Q carries log2e so qk, rh, rw all live in log2 domain
#define QSCALE (2.8284271247461903f * 1.4426950408889634f)
#define RHBIAS 25.968510736001343f   // 18 * log2(e)

// ---------------------------------------------------------------------------
// f32x2 helpers
// ---------------------------------------------------------------------------
__device__ __forceinline__ unsigned long long pk2(float a, float b) {
    unsigned long long r;
    asm("mov.b64 %0, {%1,%2};" : "=l"(r) : "f"(a), "f"(b));
    return r;
}
__device__ __forceinline__ void upk2(unsigned long long v, float& a, float& b) {
    asm("mov.b64 {%0,%1}, %2;" : "=f"(a), "=f"(b) : "l"(v));
}
__device__ __forceinline__ unsigned long long fma2(unsigned long long a,
                                                   unsigned long long b,
                                                   unsigned long long c) {
    unsigned long long r;
    asm("fma.rn.f32x2 %0, %1, %2, %3;" : "=l"(r) : "l"(a), "l"(b), "l"(c));
    return r;
}
__device__ __forceinline__ float ex2(float x) {
    float r;
    asm("ex2.approx.f32 %0, %1;" : "=f"(r) : "f"(x));
    return r;
}

// ---------------------------------------------------------------------------
// Scratch
// ---------------------------------------------------------------------------
__device__ float g_Q[NB * NHH * 8192];     // scaled by sqrt(8)*log2e
__device__ float g_K[NB * NHH * 8192];
__device__ float g_V[NB * NHH * 8192];
__device__ float g_RH[NB * NHH * 32768];   // [bh][m1][n1][n2]  (log2 domain)
__device__ float g_RW[NB * NHH * 32768];   // [bh][m1][n1][m2]  (log2 domain)
__device__ float g_attn[NB * 64 * LL];
__device__ float g_pacc[NSPLIT * 64 * 8 * LL];  // [split][bh][d][n]
__device__ float g_pS[NSPLIT * 64 * LL];        // [split][bh][n]

// ---------------------------------------------------------------------------
// Kernel 1: qkv 1x1 conv.  grid(64,8) = 512 CTAs, 192 threads, 16 pos/CTA.
// (R11 exact)
// ---------------------------------------------------------------------------
__global__ void __launch_bounds__(192) qkv_kernel(const float* __restrict__ x,
                                                  const float* __restrict__ w,
                                                  const float* __restrict__ bias)
{
    __shared__ float xs[128][20];
    const int b = blockIdx.y, chunk = blockIdx.x;
    const int tid = threadIdx.x;

    for (int i = tid; i < 128 * 16; i += 192) {
        int ci = i >> 4, p = i & 15;
        xs[ci][p] = x[(b * 128 + ci) * LL + chunk * 16 + p];
    }
    __syncthreads();

    const int oc = tid;
    unsigned long long acc[8];
#pragma unroll
    for (int j = 0; j < 8; j++) acc[j] = 0ull;

    const float4* wrow = (const float4*)(w + oc * 128);
#pragma unroll 8
    for (int c4 = 0; c4 < 32; c4++) {
        float4 w4 = __ldg(&wrow[c4]);
#pragma unroll
        for (int s = 0; s < 4; s++) {
            float wv = (s == 0) ? w4.x : (s == 1) ? w4.y : (s == 2) ? w4.z : w4.w;
            unsigned long long w2 = pk2(wv, wv);
            const ulonglong2* row = (const ulonglong2*)&xs[c4 * 4 + s][0];
#pragma unroll
            for (int j = 0; j < 4; j++) {
                ulonglong2 xv = row[j];
                acc[2 * j]     = fma2(w2, xv.x, acc[2 * j]);
                acc[2 * j + 1] = fma2(w2, xv.y, acc[2 * j + 1]);
            }
        }
    }

    float bv = bias[oc];
    float scale = 1.f;
    float* dst;
    int c;
    if (oc < 64)       { dst = g_Q; c = oc;       scale = QSCALE; }
    else if (oc < 128) { dst = g_K; c = oc - 64;  }
    else               { dst = g_V; c = oc - 128; }
    const int h = c >> 3, dk = c & 7;
    const int base = ((b * NHH + h) * 8 + dk) * LL + chunk * 16;
#pragma unroll
    for (int j = 0; j < 8; j++) {
        float a, bb;
        upk2(acc[j], a, bb);
        dst[base + 2 * j]     = (a  + bv) * scale;
        dst[base + 2 * j + 1] = (bb + bv) * scale;
    }
}

// ---------------------------------------------------------------------------
// Kernel 2: relative-logit precompute (R11 exact)
// ---------------------------------------------------------------------------
__global__ void rel_kernel(const float* __restrict__ krh,
                           const float* __restrict__ krw)
{
    __shared__ float srh[63][9], srw[63][9];
    const int bh = blockIdx.y, m1 = blockIdx.x;
    const int tid = threadIdx.x;

    if (tid < 63 * 8) {
        int r = tid >> 3, d = tid & 7;
        srh[r][d] = krh[tid];
        srw[r][d] = krw[tid];
    }
    __syncthreads();

    const int n1 = tid >> 5, lane = tid & 31;
    const float* qp = g_Q + bh * 8192 + m1 * 32 + n1;
    float q[8];
#pragma unroll
    for (int d = 0; d < 8; d++) q[d] = qp[d * LL];

    const int ih = lane - n1 + 31;
    const int iw = lane - m1 + 31;
    float rh = 0.f, rw = 0.f;
#pragma unroll
    for (int d = 0; d < 8; d++) {
        rh += q[d] * srh[ih][d];
        rw += q[d] * srw[iw][d];
    }
    const int o = ((bh * 32 + m1) * 32 + n1) * 32 + lane;
    g_RH[o] = rh;
    g_RW[o] = rw;
}

// ---------------------------------------------------------------------------
// Kernel 3: attention (R11 EXACT — best measured 73.3us).
// ---------------------------------------------------------------------------
__global__ void __launch_bounds__(128, 4) attn_kernel()
{
    extern __shared__ float sm[];
    float* sK  = sm;            // 2048
    float* sV  = sm + 2048;     // 2048
    float* sRW = sm + 4096;     // 8*16*33 = 4224
    float* sRH = sm + 8320;     // 8*16*34 = 4352

    const int bh = blockIdx.y;
    const int chunk = blockIdx.x & 1;
    const int split = blockIdx.x >> 1;
    const int tid = threadIdx.x;

    const float4* Kg4 = (const float4*)(g_K + bh * 8192 + split * 2048);
    const float4* Vg4 = (const float4*)(g_V + bh * 8192 + split * 2048);
    float4* sK4 = (float4*)sK;
    float4* sV4 = (float4*)sV;
#pragma unroll
    for (int i = tid; i < 512; i += 128) {
        sK4[i] = Kg4[i];
        sV4[i] = Vg4[i];
    }
    const float* RWg = g_RW + bh * 32768 + split * 8192 + chunk * 512;
    for (int i = tid; i < 4096; i += 128) {
        int m1l = i >> 9, r = i & 511;
        int n1l = r >> 5, m2 = r & 31;
        sRW[(m1l * 16 + n1l) * 33 + m2] = RWg[m1l * 1024 + n1l * 32 + m2];
    }
    const float* RHg = g_RH + bh * 32768 + split * 8192 + chunk * 512;
    for (int i = tid; i < 4096; i += 128) {
        int m1l = i >> 9, q = i & 511;
        int n1l = q >> 5, jq = q & 31;
        sRH[(m1l * 16 + n1l) * 34 + jq] = RHg[m1l * 1024 + q] - RHBIAS;
    }
    __syncthreads();

    const int n1t = tid >> 3, j = tid & 7;
    const int ql = n1t * 32 + j;           // queries ql + {0,8,16,24}
    const int n0 = chunk * 512 + ql;

    unsigned long long q[4][4];
#pragma unroll
    for (int qq = 0; qq < 4; qq++) {
        const ulonglong2* qg = (const ulonglong2*)(g_Q + bh * 8192 + (n0 + 8 * qq) * 8);
        ulonglong2 a = qg[0], b = qg[1];
        q[qq][0] = a.x; q[qq][1] = a.y; q[qq][2] = b.x; q[qq][3] = b.y;
    }

    unsigned long long acc[4][4];
#pragma unroll
    for (int qq = 0; qq < 4; qq++)
#pragma unroll
        for (int jj = 0; jj < 4; jj++) acc[qq][jj] = 0ull;
    float S[4] = {0.f, 0.f, 0.f, 0.f};

    for (int m1l = 0; m1l < 8; m1l++) {
        float rh[4];
#pragma unroll
        for (int qq = 0; qq < 4; qq++)
            rh[qq] = sRH[(m1l * 16 + n1t) * 34 + j + 8 * qq];
        const float* rwp = sRW + (m1l * 16 + n1t) * 33;
        const float* kb = sK + m1l * 256;
        const float* vb = sV + m1l * 256;

#pragma unroll 4
        for (int m2 = 0; m2 < 32; m2++) {
            ulonglong2 ka = *(const ulonglong2*)(kb + m2 * 8);
            ulonglong2 kc = *(const ulonglong2*)(kb + m2 * 8 + 4);
            float rw = rwp[m2];
            ulonglong2 va = *(const ulonglong2*)(vb + m2 * 8);
            ulonglong2 vc = *(const ulonglong2*)(vb + m2 * 8 + 4);

#pragma unroll
            for (int qq = 0; qq < 4; qq++) {
                unsigned long long d = pk2(rh[qq], rw);
                d = fma2(q[qq][0], ka.x, d);
                d = fma2(q[qq][1], ka.y, d);
                d = fma2(q[qq][2], kc.x, d);
                d = fma2(q[qq][3], kc.y, d);
                float a, b;
                upk2(d, a, b);
                float p = ex2(a + b);
                S[qq] += p;
                unsigned long long P = pk2(p, p);
                acc[qq][0] = fma2(P, va.x, acc[qq][0]);
                acc[qq][1] = fma2(P, va.y, acc[qq][1]);
                acc[qq][2] = fma2(P, vc.x, acc[qq][2]);
                acc[qq][3] = fma2(P, vc.y, acc[qq][3]);
            }
        }
    }

    const int pb = split * 64 + bh;
#pragma unroll
    for (int qq = 0; qq < 4; qq++) {
        const int n = n0 + 8 * qq;
#pragma unroll
        for (int jj = 0; jj < 4; jj++) {
            float a, b;
            upk2(acc[qq][jj], a, b);
            g_pacc[(pb * 8 + 2 * jj) * LL + n]     = a;
            g_pacc[(pb * 8 + 2 * jj + 1) * LL + n] = b;
        }
        g_pS[pb * LL + n] = S[qq];
    }
}

// ---------------------------------------------------------------------------
// Kernel 3b: split-K combine -> g_attn.  float4 over n. (R11 exact)
// ---------------------------------------------------------------------------
__global__ void __launch_bounds__(256) combine_kernel()
{
    const int idx = blockIdx.x * 256 + threadIdx.x;   // 16384 total
    const int bh = idx >> 8, r = idx & 255;
    const int n0 = r * 4;

    float4 S = make_float4(0.f, 0.f, 0.f, 0.f);
#pragma unroll
    for (int s = 0; s < NSPLIT; s++) {
        float4 v = *(const float4*)&g_pS[(s * 64 + bh) * LL + n0];
        S.x += v.x; S.y += v.y; S.z += v.z; S.w += v.w;
    }
    const float ix = 1.f / S.x, iy = 1.f / S.y, iz = 1.f / S.z, iw = 1.f / S.w;

#pragma unroll
    for (int d = 0; d < 8; d++) {
        float4 a = make_float4(0.f, 0.f, 0.f, 0.f);
#pragma unroll
        for (int s = 0; s < NSPLIT; s++) {
            float4 v = *(const float4*)&g_pacc[((s * 64 + bh) * 8 + d) * LL + n0];
            a.x += v.x; a.y += v.y; a.z += v.z; a.w += v.w;
        }
        a.x *= ix; a.y *= iy; a.z *= iz; a.w *= iw;
        *(float4*)&g_attn[(bh * 8 + d) * LL + n0] = a;
    }
}

// ---------------------------------------------------------------------------
// Kernel 4/5: 3x3 conv, SINGLE output row per CTA.
// grid(32 rows, 8 b, 4 oc-sixteenths) = 1024 CTAs, 128 threads
// -> ~6.9 CTAs/SM all resident = 27.7 warps/SM (2x R11's conv occupancy).
// smem: ws 9.2KB + xs[16][3][36] 6.9KB = 16.1KB.
// Thread: 32 cols x 4 og; 2 oc-pairs x 1 row. Inner loop = R11 form.
// ---------------------------------------------------------------------------
template<int CINT, bool FROM_ATTN>
__global__ void __launch_bounds__(128) conv3x3_kernel(const float* __restrict__ xin,
                                                      const float* __restrict__ wt,
                                                      const float* __restrict__ bias,
                                                      float* __restrict__ out, int oc_off)
{
    constexpr int CCH = 16;
    __shared__ float ws[CCH * 9 * 16];   // [ci][k][oc_local(16)]
    __shared__ float xs[CCH][3][36];     // [ci][row y-1..y+1][col -1..32 +pad]

    const float* __restrict__ src = FROM_ATTN ? (const float*)g_attn : xin;

    const int b = blockIdx.y, y = blockIdx.x;
    const int ocbase = blockIdx.z * 16;
    const int tid = threadIdx.x;
    const int x = tid & 31, og = tid >> 5;

    unsigned long long acc[2];
    acc[0] = acc[1] = 0ull;

    for (int c0 = 0; c0 < CINT; c0 += CCH) {
        __syncthreads();
        for (int i = tid; i < CCH * 9 * 16; i += 128) {
            int oc = i & 15;
            int r  = i >> 4;            // ci*9 + k
            int k  = r % 9, ci = r / 9;
            ws[i] = wt[((ocbase + oc) * CINT + c0 + ci) * 9 + k];
        }
        for (int i = tid; i < CCH * 3 * 34; i += 128) {
            int ci = i / 102;
            int r2 = i - ci * 102;
            int rr = r2 / 34, col = r2 - rr * 34;
            int yy = y - 1 + rr, xx = col - 1;
            float v = 0.f;
            if (yy >= 0 && yy < 32 && xx >= 0 && xx < 32)
                v = src[(b * CINT + c0 + ci) * LL + yy * 32 + xx];
            xs[ci][rr][col] = v;
        }
        __syncthreads();

        for (int ci = 0; ci < CCH; ci++) {
            unsigned long long x2[3][3];
#pragma unroll
            for (int rr = 0; rr < 3; rr++)
#pragma unroll
                for (int c = 0; c < 3; c++) {
                    float v = xs[ci][rr][x + c];
                    x2[rr][c] = pk2(v, v);
                }
            const float* wp = &ws[ci * 144 + og * 4];
#pragma unroll
            for (int k = 0; k < 9; k++) {
                const int ky = k / 3, c = k - ky * 3;
                ulonglong2 wA = *(const ulonglong2*)(wp + k * 16);
                acc[0] = fma2(wA.x, x2[ky][c], acc[0]);
                acc[1] = fma2(wA.y, x2[ky][c], acc[1]);
            }
        }
    }

#pragma unroll
    for (int p = 0; p < 2; p++) {
        const int oc0 = ocbase + og * 4 + 2 * p;
        float b0 = bias[oc0], b1 = bias[oc0 + 1];
        float a, bb;
        upk2(acc[p], a, bb);
        out[(b * 128 + oc_off + oc0) * LL + y * 32 + x]     = a + b0;
        out[(b * 128 + oc_off + oc0 + 1) * LL + y * 32 + x] = bb + b1;
    }
}

// ---------------------------------------------------------------------------
// Launch
// ---------------------------------------------------------------------------
extern "C" void kernel_launch(void* const* d_in, const int* in_sizes, int n_in,
                              void* d_out, int out_size)
{
    const float* x         = (const float*)d_in[0];
    const float* w_general = (const float*)d_in[1];
    const float* b_general = (const float*)d_in[2];
    const float* w_qkv     = (const float*)d_in[3];
    const float* b_qkv     = (const float*)d_in[4];
    const float* w_out     = (const float*)d_in[5];
    const float* b_out     = (const float*)d_in[6];
    const float* krh       = (const float*)d_in[7];
    const float* krw       = (const float*)d_in[8];
    float* out = (float*)d_out;

    static cudaStream_t s2 = nullptr;
    static cudaEvent_t ev_fork = nullptr, ev_join = nullptr;
    if (s2 == nullptr) {
        cudaStreamCreateWithFlags(&s2, cudaStreamNonBlocking);
        cudaEventCreateWithFlags(&ev_fork, cudaEventDisableTiming);
        cudaEventCreateWithFlags(&ev_join, cudaEventDisableTiming);
        cudaFuncSetAttribute(attn_kernel,
                             cudaFuncAttributeMaxDynamicSharedMemorySize, 51200);
    }

    cudaEventRecord(ev_fork, 0);
    cudaStreamWaitEvent(s2, ev_fork, 0);
    conv3x3_kernel<128, false><<<dim3(32, NB, 4), 128, 0, s2>>>(x, w_general, b_general, out, 0);
    cudaEventRecord(ev_join, s2);

    qkv_kernel<<<dim3(64, NB), 192>>>(x, w_qkv, b_qkv);
    rel_kernel<<<dim3(32, NB * NHH), 1024>>>(krh, krw);
    attn_kernel<<<dim3(8, NB * NHH), 128, 51200>>>();
    combine_kernel<<<64, 256>>>();
    conv3x3_kernel<64, true><<<dim3(32, NB, 4), 128>>>(nullptr, w_out, b_out, out, 64);

    cudaStreamWaitEvent(0, ev_join, 0);
}

// round 16
// speedup vs baseline: 1.3973x; 1.3973x over previous
#include <cuda_runtime.h>

#define NB   8
#define NHH  8
#define LL   1024
#define NSPLIT 4
// sqrt(8) * log2(e): Q carries log2e so qk, rh, rw all live in log2 domain
#define QSCALE (2.8284271247461903f * 1.4426950408889634f)
#define RHBIAS 25.968510736001343f   // 18 * log2(e)

// ---------------------------------------------------------------------------
// f32x2 helpers
// ---------------------------------------------------------------------------
__device__ __forceinline__ unsigned long long pk2(float a, float b) {
    unsigned long long r;
    asm("mov.b64 %0, {%1,%2};" : "=l"(r) : "f"(a), "f"(b));
    return r;
}
__device__ __forceinline__ void upk2(unsigned long long v, float& a, float& b) {
    asm("mov.b64 {%0,%1}, %2;" : "=f"(a), "=f"(b) : "l"(v));
}
__device__ __forceinline__ unsigned long long fma2(unsigned long long a,
                                                   unsigned long long b,
                                                   unsigned long long c) {
    unsigned long long r;
    asm("fma.rn.f32x2 %0, %1, %2, %3;" : "=l"(r) : "l"(a), "l"(b), "l"(c));
    return r;
}
__device__ __forceinline__ float ex2(float x) {
    float r;
    asm("ex2.approx.f32 %0, %1;" : "=f"(r) : "f"(x));
    return r;
}

// ---------------------------------------------------------------------------
// Scratch
// ---------------------------------------------------------------------------
__device__ float g_Q[NB * NHH * 8192];     // scaled by sqrt(8)*log2e
__device__ float g_K[NB * NHH * 8192];
__device__ float g_V[NB * NHH * 8192];
__device__ float g_RH[NB * NHH * 32768];   // [bh][m1][n1][n2]  (log2 domain)
__device__ float g_RW[NB * NHH * 32768];   // [bh][m1][n1][m2]  (log2 domain)
__device__ float g_attn[NB * 64 * LL];
__device__ float g_pacc[NSPLIT * 64 * 8 * LL];  // [split][bh][d][n]
__device__ float g_pS[NSPLIT * 64 * LL];        // [split][bh][n]
__device__ float g_wtg[1152 * 64];              // w_general transposed [ci*9+k][oc]
__device__ float g_wto[576 * 64];               // w_out transposed [ci*9+k][oc]

// ---------------------------------------------------------------------------
// Kernel 0: weight transpose  in[oc][R] -> out[r][64]   (OC fixed = 64)
// ---------------------------------------------------------------------------
__global__ void __launch_bounds__(256) transpose_w_kernel(const float* __restrict__ in,
                                                          float* __restrict__ out, int R)
{
    const int idx = blockIdx.x * 256 + threadIdx.x;
    if (idx < 64 * R) {
        const int oc = idx & 63, r = idx >> 6;
        out[idx] = in[oc * R + r];     // write coalesced, read scattered (one-off)
    }
}

// ---------------------------------------------------------------------------
// Kernel 1: qkv 1x1 conv.  grid(64,8) = 512 CTAs, 192 threads. (R11 exact)
// ---------------------------------------------------------------------------
__global__ void __launch_bounds__(192) qkv_kernel(const float* __restrict__ x,
                                                  const float* __restrict__ w,
                                                  const float* __restrict__ bias)
{
    __shared__ float xs[128][20];
    const int b = blockIdx.y, chunk = blockIdx.x;
    const int tid = threadIdx.x;

    for (int i = tid; i < 128 * 16; i += 192) {
        int ci = i >> 4, p = i & 15;
        xs[ci][p] = x[(b * 128 + ci) * LL + chunk * 16 + p];
    }
    __syncthreads();

    const int oc = tid;
    unsigned long long acc[8];
#pragma unroll
    for (int j = 0; j < 8; j++) acc[j] = 0ull;

    const float4* wrow = (const float4*)(w + oc * 128);
#pragma unroll 8
    for (int c4 = 0; c4 < 32; c4++) {
        float4 w4 = __ldg(&wrow[c4]);
#pragma unroll
        for (int s = 0; s < 4; s++) {
            float wv = (s == 0) ? w4.x : (s == 1) ? w4.y : (s == 2) ? w4.z : w4.w;
            unsigned long long w2 = pk2(wv, wv);
            const ulonglong2* row = (const ulonglong2*)&xs[c4 * 4 + s][0];
#pragma unroll
            for (int j = 0; j < 4; j++) {
                ulonglong2 xv = row[j];
                acc[2 * j]     = fma2(w2, xv.x, acc[2 * j]);
                acc[2 * j + 1] = fma2(w2, xv.y, acc[2 * j + 1]);
            }
        }
    }

    float bv = bias[oc];
    float scale = 1.f;
    float* dst;
    int c;
    if (oc < 64)       { dst = g_Q; c = oc;       scale = QSCALE; }
    else if (oc < 128) { dst = g_K; c = oc - 64;  }
    else               { dst = g_V; c = oc - 128; }
    const int h = c >> 3, dk = c & 7;
    const int base = ((b * NHH + h) * 8 + dk) * LL + chunk * 16;
#pragma unroll
    for (int j = 0; j < 8; j++) {
        float a, bb;
        upk2(acc[j], a, bb);
        dst[base + 2 * j]     = (a  + bv) * scale;
        dst[base + 2 * j + 1] = (bb + bv) * scale;
    }
}

// ---------------------------------------------------------------------------
// Kernel 2: relative-logit precompute (R11 exact)
// ---------------------------------------------------------------------------
__global__ void rel_kernel(const float* __restrict__ krh,
                           const float* __restrict__ krw)
{
    __shared__ float srh[63][9], srw[63][9];
    const int bh = blockIdx.y, m1 = blockIdx.x;
    const int tid = threadIdx.x;

    if (tid < 63 * 8) {
        int r = tid >> 3, d = tid & 7;
        srh[r][d] = krh[tid];
        srw[r][d] = krw[tid];
    }
    __syncthreads();

    const int n1 = tid >> 5, lane = tid & 31;
    const float* qp = g_Q + bh * 8192 + m1 * 32 + n1;
    float q[8];
#pragma unroll
    for (int d = 0; d < 8; d++) q[d] = qp[d * LL];

    const int ih = lane - n1 + 31;
    const int iw = lane - m1 + 31;
    float rh = 0.f, rw = 0.f;
#pragma unroll
    for (int d = 0; d < 8; d++) {
        rh += q[d] * srh[ih][d];
        rw += q[d] * srw[iw][d];
    }
    const int o = ((bh * 32 + m1) * 32 + n1) * 32 + lane;
    g_RH[o] = rh;
    g_RW[o] = rw;
}

// ---------------------------------------------------------------------------
// Kernel 3: attention (R11 EXACT — best measured 73.3us).
// ---------------------------------------------------------------------------
__global__ void __launch_bounds__(128, 4) attn_kernel()
{
    extern __shared__ float sm[];
    float* sK  = sm;            // 2048
    float* sV  = sm + 2048;     // 2048
    float* sRW = sm + 4096;     // 8*16*33 = 4224
    float* sRH = sm + 8320;     // 8*16*34 = 4352

    const int bh = blockIdx.y;
    const int chunk = blockIdx.x & 1;
    const int split = blockIdx.x >> 1;
    const int tid = threadIdx.x;

    const float4* Kg4 = (const float4*)(g_K + bh * 8192 + split * 2048);
    const float4* Vg4 = (const float4*)(g_V + bh * 8192 + split * 2048);
    float4* sK4 = (float4*)sK;
    float4* sV4 = (float4*)sV;
#pragma unroll
    for (int i = tid; i < 512; i += 128) {
        sK4[i] = Kg4[i];
        sV4[i] = Vg4[i];
    }
    const float* RWg = g_RW + bh * 32768 + split * 8192 + chunk * 512;
    for (int i = tid; i < 4096; i += 128) {
        int m1l = i >> 9, r = i & 511;
        int n1l = r >> 5, m2 = r & 31;
        sRW[(m1l * 16 + n1l) * 33 + m2] = RWg[m1l * 1024 + n1l * 32 + m2];
    }
    const float* RHg = g_RH + bh * 32768 + split * 8192 + chunk * 512;
    for (int i = tid; i < 4096; i += 128) {
        int m1l = i >> 9, q = i & 511;
        int n1l = q >> 5, jq = q & 31;
        sRH[(m1l * 16 + n1l) * 34 + jq] = RHg[m1l * 1024 + q] - RHBIAS;
    }
    __syncthreads();

    const int n1t = tid >> 3, j = tid & 7;
    const int ql = n1t * 32 + j;           // queries ql + {0,8,16,24}
    const int n0 = chunk * 512 + ql;

    unsigned long long q[4][4];
#pragma unroll
    for (int qq = 0; qq < 4; qq++) {
        const ulonglong2* qg = (const ulonglong2*)(g_Q + bh * 8192 + (n0 + 8 * qq) * 8);
        ulonglong2 a = qg[0], b = qg[1];
        q[qq][0] = a.x; q[qq][1] = a.y; q[qq][2] = b.x; q[qq][3] = b.y;
    }

    unsigned long long acc[4][4];
#pragma unroll
    for (int qq = 0; qq < 4; qq++)
#pragma unroll
        for (int jj = 0; jj < 4; jj++) acc[qq][jj] = 0ull;
    float S[4] = {0.f, 0.f, 0.f, 0.f};

    for (int m1l = 0; m1l < 8; m1l++) {
        float rh[4];
#pragma unroll
        for (int qq = 0; qq < 4; qq++)
            rh[qq] = sRH[(m1l * 16 + n1t) * 34 + j + 8 * qq];
        const float* rwp = sRW + (m1l * 16 + n1t) * 33;
        const float* kb = sK + m1l * 256;
        const float* vb = sV + m1l * 256;

#pragma unroll 4
        for (int m2 = 0; m2 < 32; m2++) {
            ulonglong2 ka = *(const ulonglong2*)(kb + m2 * 8);
            ulonglong2 kc = *(const ulonglong2*)(kb + m2 * 8 + 4);
            float rw = rwp[m2];
            ulonglong2 va = *(const ulonglong2*)(vb + m2 * 8);
            ulonglong2 vc = *(const ulonglong2*)(vb + m2 * 8 + 4);

#pragma unroll
            for (int qq = 0; qq < 4; qq++) {
                unsigned long long d = pk2(rh[qq], rw);
                d = fma2(q[qq][0], ka.x, d);
                d = fma2(q[qq][1], ka.y, d);
                d = fma2(q[qq][2], kc.x, d);
                d = fma2(q[qq][3], kc.y, d);
                float a, b;
                upk2(d, a, b);
                float p = ex2(a + b);
                S[qq] += p;
                unsigned long long P = pk2(p, p);
                acc[qq][0] = fma2(P, va.x, acc[qq][0]);
                acc[qq][1] = fma2(P, va.y, acc[qq][1]);
                acc[qq][2] = fma2(P, vc.x, acc[qq][2]);
                acc[qq][3] = fma2(P, vc.y, acc[qq][3]);
            }
        }
    }

    const int pb = split * 64 + bh;
#pragma unroll
    for (int qq = 0; qq < 4; qq++) {
        const int n = n0 + 8 * qq;
#pragma unroll
        for (int jj = 0; jj < 4; jj++) {
            float a, b;
            upk2(acc[qq][jj], a, b);
            g_pacc[(pb * 8 + 2 * jj) * LL + n]     = a;
            g_pacc[(pb * 8 + 2 * jj + 1) * LL + n] = b;
        }
        g_pS[pb * LL + n] = S[qq];
    }
}

// ---------------------------------------------------------------------------
// Kernel 3b: split-K combine -> g_attn.  float4 over n. (R11 exact)
// ---------------------------------------------------------------------------
__global__ void __launch_bounds__(256) combine_kernel()
{
    const int idx = blockIdx.x * 256 + threadIdx.x;   // 16384 total
    const int bh = idx >> 8, r = idx & 255;
    const int n0 = r * 4;

    float4 S = make_float4(0.f, 0.f, 0.f, 0.f);
#pragma unroll
    for (int s = 0; s < NSPLIT; s++) {
        float4 v = *(const float4*)&g_pS[(s * 64 + bh) * LL + n0];
        S.x += v.x; S.y += v.y; S.z += v.z; S.w += v.w;
    }
    const float ix = 1.f / S.x, iy = 1.f / S.y, iz = 1.f / S.z, iw = 1.f / S.w;

#pragma unroll
    for (int d = 0; d < 8; d++) {
        float4 a = make_float4(0.f, 0.f, 0.f, 0.f);
#pragma unroll
        for (int s = 0; s < NSPLIT; s++) {
            float4 v = *(const float4*)&g_pacc[((s * 64 + bh) * 8 + d) * LL + n0];
            a.x += v.x; a.y += v.y; a.z += v.z; a.w += v.w;
        }
        a.x *= ix; a.y *= iy; a.z *= iz; a.w *= iw;
        *(float4*)&g_attn[(bh * 8 + d) * LL + n0] = a;
    }
}

// ---------------------------------------------------------------------------
// Kernel 4/5: 3x3 conv (R11 structure). grid(16,8,4), 128 threads.
// Weights read from PRE-TRANSPOSED layout [ci*9+k][oc64]: staging LDG is
// coalesced (2 sectors/warp vs 32 before). Compute loop byte-identical R11.
// ---------------------------------------------------------------------------
template<int CINT, bool FROM_ATTN>
__global__ void __launch_bounds__(128) conv3x3_kernel(const float* __restrict__ xin,
                                                      const float* __restrict__ wtg,
                                                      const float* __restrict__ bias,
                                                      float* __restrict__ out, int oc_off)
{
    constexpr int CCH = 16;
    __shared__ float ws[CCH * 9 * 16];   // [r=ci*9+k][oc_local(16)]
    __shared__ float xs[CCH][4][36];

    const float* __restrict__ src = FROM_ATTN ? (const float*)g_attn : xin;

    const int b = blockIdx.y, y0 = blockIdx.x * 2;
    const int ocbase = blockIdx.z * 16;
    const int tid = threadIdx.x;
    const int x = tid & 31, og = tid >> 5;

    unsigned long long acc[2][2];
    acc[0][0] = acc[0][1] = acc[1][0] = acc[1][1] = 0ull;

    for (int c0 = 0; c0 < CINT; c0 += CCH) {
        __syncthreads();
        // weights from transposed layout: LDG coalesced, STS conflict-free
        {
            const float* wsrc = wtg + (c0 * 9) * 64 + ocbase;
            for (int i = tid; i < CCH * 9 * 16; i += 128) {
                int oc = i & 15;
                int r  = i >> 4;
                ws[i] = wsrc[r * 64 + oc];
            }
        }
        for (int i = tid; i < CCH * 4 * 34; i += 128) {
            int ci = i / 136;
            int r2 = i - ci * 136;
            int rr = r2 / 34, col = r2 - rr * 34;
            int yy = y0 - 1 + rr, xx = col - 1;
            float v = 0.f;
            if (yy >= 0 && yy < 32 && xx >= 0 && xx < 32)
                v = src[(b * CINT + c0 + ci) * LL + yy * 32 + xx];
            xs[ci][rr][col] = v;
        }
        __syncthreads();

        for (int ci = 0; ci < CCH; ci++) {
            unsigned long long x2[4][3];
#pragma unroll
            for (int rr = 0; rr < 4; rr++)
#pragma unroll
                for (int c = 0; c < 3; c++) {
                    float v = xs[ci][rr][x + c];
                    x2[rr][c] = pk2(v, v);
                }
            const float* wp = &ws[ci * 144 + og * 4];
#pragma unroll
            for (int k = 0; k < 9; k++) {
                const int ky = k / 3, c = k - ky * 3;
                ulonglong2 wA = *(const ulonglong2*)(wp + k * 16);
                acc[0][0] = fma2(wA.x, x2[ky][c],     acc[0][0]);
                acc[0][1] = fma2(wA.x, x2[ky + 1][c], acc[0][1]);
                acc[1][0] = fma2(wA.y, x2[ky][c],     acc[1][0]);
                acc[1][1] = fma2(wA.y, x2[ky + 1][c], acc[1][1]);
            }
        }
    }

#pragma unroll
    for (int p = 0; p < 2; p++) {
        const int oc0 = ocbase + og * 4 + 2 * p;
        float b0 = bias[oc0], b1 = bias[oc0 + 1];
#pragma unroll
        for (int r = 0; r < 2; r++) {
            float a, bb;
            upk2(acc[p][r], a, bb);
            out[(b * 128 + oc_off + oc0) * LL + (y0 + r) * 32 + x]     = a + b0;
            out[(b * 128 + oc_off + oc0 + 1) * LL + (y0 + r) * 32 + x] = bb + b1;
        }
    }
}

// ---------------------------------------------------------------------------
// Launch
// ---------------------------------------------------------------------------
extern "C" void kernel_launch(void* const* d_in, const int* in_sizes, int n_in,
                              void* d_out, int out_size)
{
    const float* x         = (const float*)d_in[0];
    const float* w_general = (const float*)d_in[1];
    const float* b_general = (const float*)d_in[2];
    const float* w_qkv     = (const float*)d_in[3];
    const float* b_qkv     = (const float*)d_in[4];
    const float* w_out     = (const float*)d_in[5];
    const float* b_out     = (const float*)d_in[6];
    const float* krh       = (const float*)d_in[7];
    const float* krw       = (const float*)d_in[8];
    float* out = (float*)d_out;

    static cudaStream_t s2 = nullptr;
    static cudaEvent_t ev_fork = nullptr, ev_join = nullptr;
    static float *p_wtg = nullptr, *p_wto = nullptr;
    if (s2 == nullptr) {
        cudaStreamCreateWithFlags(&s2, cudaStreamNonBlocking);
        cudaEventCreateWithFlags(&ev_fork, cudaEventDisableTiming);
        cudaEventCreateWithFlags(&ev_join, cudaEventDisableTiming);
        cudaFuncSetAttribute(attn_kernel,
                             cudaFuncAttributeMaxDynamicSharedMemorySize, 51200);
        cudaGetSymbolAddress((void**)&p_wtg, g_wtg);
        cudaGetSymbolAddress((void**)&p_wto, g_wto);
    }

    // weight transposes (main stream, before fork)
    transpose_w_kernel<<<288, 256>>>(w_general, p_wtg, 1152);
    transpose_w_kernel<<<144, 256>>>(w_out, p_wto, 576);

    cudaEventRecord(ev_fork, 0);
    cudaStreamWaitEvent(s2, ev_fork, 0);
    conv3x3_kernel<128, false><<<dim3(16, NB, 4), 128, 0, s2>>>(x, p_wtg, b_general, out, 0);
    cudaEventRecord(ev_join, s2);

    qkv_kernel<<<dim3(64, NB), 192>>>(x, w_qkv, b_qkv);
    rel_kernel<<<dim3(32, NB * NHH), 1024>>>(krh, krw);
    attn_kernel<<<dim3(8, NB * NHH), 128, 51200>>>();
    combine_kernel<<<64, 256>>>();
    conv3x3_kernel<64, true><<<dim3(16, NB, 4), 128>>>(nullptr, p_wto, b_out, out, 64);

    cudaStreamWaitEvent(0, ev_join, 0);
}

// round 17
// speedup vs baseline: 1.4384x; 1.0294x over previous
#include <cuda_runtime.h>

#define NB   8
#define NHH  8
#define LL   1024
#define NSPLIT 4
// sqrt(8) * log2(e): Q carries log2e so qk, rh, rw all live in log2 domain
#define QSCALE (2.8284271247461903f * 1.4426950408889634f)
#define RHBIAS 25.968510736001343f   // 18 * log2(e)

// ---------------------------------------------------------------------------
// f32x2 helpers
// ---------------------------------------------------------------------------
__device__ __forceinline__ unsigned long long pk2(float a, float b) {
    unsigned long long r;
    asm("mov.b64 %0, {%1,%2};" : "=l"(r) : "f"(a), "f"(b));
    return r;
}
__device__ __forceinline__ void upk2(unsigned long long v, float& a, float& b) {
    asm("mov.b64 {%0,%1}, %2;" : "=f"(a), "=f"(b) : "l"(v));
}
__device__ __forceinline__ unsigned long long fma2(unsigned long long a,
                                                   unsigned long long b,
                                                   unsigned long long c) {
    unsigned long long r;
    asm("fma.rn.f32x2 %0, %1, %2, %3;" : "=l"(r) : "l"(a), "l"(b), "l"(c));
    return r;
}
__device__ __forceinline__ float ex2(float x) {
    float r;
    asm("ex2.approx.f32 %0, %1;" : "=f"(r) : "f"(x));
    return r;
}

// ---------------------------------------------------------------------------
// Scratch
// ---------------------------------------------------------------------------
__device__ float g_Q[NB * NHH * 8192];     // scaled by sqrt(8)*log2e
__device__ float g_K[NB * NHH * 8192];
__device__ float g_V[NB * NHH * 8192];
__device__ float g_RH[NB * NHH * 32768];   // [bh][m1][n1][n2]  (log2 domain)
__device__ float g_RW[NB * NHH * 32768];   // [bh][m1][n1][m2]  (log2 domain)
__device__ float g_attn[NB * 64 * LL];
__device__ float g_pacc[NSPLIT * 64 * 8 * LL];  // [split][bh][d][n]
__device__ float g_pS[NSPLIT * 64 * LL];        // [split][bh][n]
__device__ float g_wtg[1152 * 64];              // w_general transposed [ci*9+k][oc]
__device__ float g_wto[576 * 64];               // w_out transposed [ci*9+k][oc]
__device__ float g_wqt[128 * 192];              // w_qkv transposed [ci][oc]

// ---------------------------------------------------------------------------
// Kernel 0: weight transpose  in[oc][R] -> out[r][OC]
// ---------------------------------------------------------------------------
__global__ void __launch_bounds__(256) transpose_w_kernel(const float* __restrict__ in,
                                                          float* __restrict__ out,
                                                          int R, int OC)
{
    const int idx = blockIdx.x * 256 + threadIdx.x;
    if (idx < OC * R) {
        const int oc = idx % OC, r = idx / OC;
        out[idx] = in[oc * R + r];     // write coalesced, read scattered (one-off)
    }
}

// ---------------------------------------------------------------------------
// Kernel 1: qkv 1x1 conv.  grid(64,8) = 512 CTAs, 192 threads, 16 pos/CTA.
// Weights from TRANSPOSED layout [ci][oc192]: coalesced scalar LDG per ci.
// ---------------------------------------------------------------------------
__global__ void __launch_bounds__(192) qkv_kernel(const float* __restrict__ x,
                                                  const float* __restrict__ bias)
{
    __shared__ float xs[128][20];
    const int b = blockIdx.y, chunk = blockIdx.x;
    const int tid = threadIdx.x;

    for (int i = tid; i < 128 * 16; i += 192) {
        int ci = i >> 4, p = i & 15;
        xs[ci][p] = x[(b * 128 + ci) * LL + chunk * 16 + p];
    }
    __syncthreads();

    const int oc = tid;
    unsigned long long acc[8];
#pragma unroll
    for (int j = 0; j < 8; j++) acc[j] = 0ull;

    const float* wcol = g_wqt + oc;    // stride 192, coalesced across threads
#pragma unroll 8
    for (int ci = 0; ci < 128; ci++) {
        float wv = wcol[ci * 192];
        unsigned long long w2 = pk2(wv, wv);
        const ulonglong2* row = (const ulonglong2*)&xs[ci][0];
#pragma unroll
        for (int j = 0; j < 4; j++) {
            ulonglong2 xv = row[j];
            acc[2 * j]     = fma2(w2, xv.x, acc[2 * j]);
            acc[2 * j + 1] = fma2(w2, xv.y, acc[2 * j + 1]);
        }
    }

    float bv = bias[oc];
    float scale = 1.f;
    float* dst;
    int c;
    if (oc < 64)       { dst = g_Q; c = oc;       scale = QSCALE; }
    else if (oc < 128) { dst = g_K; c = oc - 64;  }
    else               { dst = g_V; c = oc - 128; }
    const int h = c >> 3, dk = c & 7;
    const int base = ((b * NHH + h) * 8 + dk) * LL + chunk * 16;
#pragma unroll
    for (int j = 0; j < 8; j++) {
        float a, bb;
        upk2(acc[j], a, bb);
        dst[base + 2 * j]     = (a  + bv) * scale;
        dst[base + 2 * j + 1] = (bb + bv) * scale;
    }
}

// ---------------------------------------------------------------------------
// Kernel 2: relative-logit precompute (R11 exact)
// ---------------------------------------------------------------------------
__global__ void rel_kernel(const float* __restrict__ krh,
                           const float* __restrict__ krw)
{
    __shared__ float srh[63][9], srw[63][9];
    const int bh = blockIdx.y, m1 = blockIdx.x;
    const int tid = threadIdx.x;

    if (tid < 63 * 8) {
        int r = tid >> 3, d = tid & 7;
        srh[r][d] = krh[tid];
        srw[r][d] = krw[tid];
    }
    __syncthreads();

    const int n1 = tid >> 5, lane = tid & 31;
    const float* qp = g_Q + bh * 8192 + m1 * 32 + n1;
    float q[8];
#pragma unroll
    for (int d = 0; d < 8; d++) q[d] = qp[d * LL];

    const int ih = lane - n1 + 31;
    const int iw = lane - m1 + 31;
    float rh = 0.f, rw = 0.f;
#pragma unroll
    for (int d = 0; d < 8; d++) {
        rh += q[d] * srh[ih][d];
        rw += q[d] * srw[iw][d];
    }
    const int o = ((bh * 32 + m1) * 32 + n1) * 32 + lane;
    g_RH[o] = rh;
    g_RW[o] = rw;
}

// ---------------------------------------------------------------------------
// Kernel 3: attention (R11 EXACT — best measured 73.3us).
// ---------------------------------------------------------------------------
__global__ void __launch_bounds__(128, 4) attn_kernel()
{
    extern __shared__ float sm[];
    float* sK  = sm;            // 2048
    float* sV  = sm + 2048;     // 2048
    float* sRW = sm + 4096;     // 8*16*33 = 4224
    float* sRH = sm + 8320;     // 8*16*34 = 4352

    const int bh = blockIdx.y;
    const int chunk = blockIdx.x & 1;
    const int split = blockIdx.x >> 1;
    const int tid = threadIdx.x;

    const float4* Kg4 = (const float4*)(g_K + bh * 8192 + split * 2048);
    const float4* Vg4 = (const float4*)(g_V + bh * 8192 + split * 2048);
    float4* sK4 = (float4*)sK;
    float4* sV4 = (float4*)sV;
#pragma unroll
    for (int i = tid; i < 512; i += 128) {
        sK4[i] = Kg4[i];
        sV4[i] = Vg4[i];
    }
    const float* RWg = g_RW + bh * 32768 + split * 8192 + chunk * 512;
    for (int i = tid; i < 4096; i += 128) {
        int m1l = i >> 9, r = i & 511;
        int n1l = r >> 5, m2 = r & 31;
        sRW[(m1l * 16 + n1l) * 33 + m2] = RWg[m1l * 1024 + n1l * 32 + m2];
    }
    const float* RHg = g_RH + bh * 32768 + split * 8192 + chunk * 512;
    for (int i = tid; i < 4096; i += 128) {
        int m1l = i >> 9, q = i & 511;
        int n1l = q >> 5, jq = q & 31;
        sRH[(m1l * 16 + n1l) * 34 + jq] = RHg[m1l * 1024 + q] - RHBIAS;
    }
    __syncthreads();

    const int n1t = tid >> 3, j = tid & 7;
    const int ql = n1t * 32 + j;           // queries ql + {0,8,16,24}
    const int n0 = chunk * 512 + ql;

    unsigned long long q[4][4];
#pragma unroll
    for (int qq = 0; qq < 4; qq++) {
        const ulonglong2* qg = (const ulonglong2*)(g_Q + bh * 8192 + (n0 + 8 * qq) * 8);
        ulonglong2 a = qg[0], b = qg[1];
        q[qq][0] = a.x; q[qq][1] = a.y; q[qq][2] = b.x; q[qq][3] = b.y;
    }

    unsigned long long acc[4][4];
#pragma unroll
    for (int qq = 0; qq < 4; qq++)
#pragma unroll
        for (int jj = 0; jj < 4; jj++) acc[qq][jj] = 0ull;
    float S[4] = {0.f, 0.f, 0.f, 0.f};

    for (int m1l = 0; m1l < 8; m1l++) {
        float rh[4];
#pragma unroll
        for (int qq = 0; qq < 4; qq++)
            rh[qq] = sRH[(m1l * 16 + n1t) * 34 + j + 8 * qq];
        const float* rwp = sRW + (m1l * 16 + n1t) * 33;
        const float* kb = sK + m1l * 256;
        const float* vb = sV + m1l * 256;

#pragma unroll 4
        for (int m2 = 0; m2 < 32; m2++) {
            ulonglong2 ka = *(const ulonglong2*)(kb + m2 * 8);
            ulonglong2 kc = *(const ulonglong2*)(kb + m2 * 8 + 4);
            float rw = rwp[m2];
            ulonglong2 va = *(const ulonglong2*)(vb + m2 * 8);
            ulonglong2 vc = *(const ulonglong2*)(vb + m2 * 8 + 4);

#pragma unroll
            for (int qq = 0; qq < 4; qq++) {
                unsigned long long d = pk2(rh[qq], rw);
                d = fma2(q[qq][0], ka.x, d);
                d = fma2(q[qq][1], ka.y, d);
                d = fma2(q[qq][2], kc.x, d);
                d = fma2(q[qq][3], kc.y, d);
                float a, b;
                upk2(d, a, b);
                float p = ex2(a + b);
                S[qq] += p;
                unsigned long long P = pk2(p, p);
                acc[qq][0] = fma2(P, va.x, acc[qq][0]);
                acc[qq][1] = fma2(P, va.y, acc[qq][1]);
                acc[qq][2] = fma2(P, vc.x, acc[qq][2]);
                acc[qq][3] = fma2(P, vc.y, acc[qq][3]);
            }
        }
    }

    const int pb = split * 64 + bh;
#pragma unroll
    for (int qq = 0; qq < 4; qq++) {
        const int n = n0 + 8 * qq;
#pragma unroll
        for (int jj = 0; jj < 4; jj++) {
            float a, b;
            upk2(acc[qq][jj], a, b);
            g_pacc[(pb * 8 + 2 * jj) * LL + n]     = a;
            g_pacc[(pb * 8 + 2 * jj + 1) * LL + n] = b;
        }
        g_pS[pb * LL + n] = S[qq];
    }
}

// ---------------------------------------------------------------------------
// Kernel 3b: split-K combine -> g_attn.  float4 over n. (R11 exact)
// ---------------------------------------------------------------------------
__global__ void __launch_bounds__(256) combine_kernel()
{
    const int idx = blockIdx.x * 256 + threadIdx.x;   // 16384 total
    const int bh = idx >> 8, r = idx & 255;
    const int n0 = r * 4;

    float4 S = make_float4(0.f, 0.f, 0.f, 0.f);
#pragma unroll
    for (int s = 0; s < NSPLIT; s++) {
        float4 v = *(const float4*)&g_pS[(s * 64 + bh) * LL + n0];
        S.x += v.x; S.y += v.y; S.z += v.z; S.w += v.w;
    }
    const float ix = 1.f / S.x, iy = 1.f / S.y, iz = 1.f / S.z, iw = 1.f / S.w;

#pragma unroll
    for (int d = 0; d < 8; d++) {
        float4 a = make_float4(0.f, 0.f, 0.f, 0.f);
#pragma unroll
        for (int s = 0; s < NSPLIT; s++) {
            float4 v = *(const float4*)&g_pacc[((s * 64 + bh) * 8 + d) * LL + n0];
            a.x += v.x; a.y += v.y; a.z += v.z; a.w += v.w;
        }
        a.x *= ix; a.y *= iy; a.z *= iz; a.w *= iw;
        *(float4*)&g_attn[(bh * 8 + d) * LL + n0] = a;
    }
}

// ---------------------------------------------------------------------------
// Kernel 4/5: 3x3 conv (R16 exact — transposed weights). grid(16,8,4), 128 thr.
// ---------------------------------------------------------------------------
template<int CINT, bool FROM_ATTN>
__global__ void __launch_bounds__(128) conv3x3_kernel(const float* __restrict__ xin,
                                                      const float* __restrict__ wtg,
                                                      const float* __restrict__ bias,
                                                      float* __restrict__ out, int oc_off)
{
    constexpr int CCH = 16;
    __shared__ float ws[CCH * 9 * 16];   // [r=ci*9+k][oc_local(16)]
    __shared__ float xs[CCH][4][36];

    const float* __restrict__ src = FROM_ATTN ? (const float*)g_attn : xin;

    const int b = blockIdx.y, y0 = blockIdx.x * 2;
    const int ocbase = blockIdx.z * 16;
    const int tid = threadIdx.x;
    const int x = tid & 31, og = tid >> 5;

    unsigned long long acc[2][2];
    acc[0][0] = acc[0][1] = acc[1][0] = acc[1][1] = 0ull;

    for (int c0 = 0; c0 < CINT; c0 += CCH) {
        __syncthreads();
        {
            const float* wsrc = wtg + (c0 * 9) * 64 + ocbase;
            for (int i = tid; i < CCH * 9 * 16; i += 128) {
                int oc = i & 15;
                int r  = i >> 4;
                ws[i] = wsrc[r * 64 + oc];
            }
        }
        for (int i = tid; i < CCH * 4 * 34; i += 128) {
            int ci = i / 136;
            int r2 = i - ci * 136;
            int rr = r2 / 34, col = r2 - rr * 34;
            int yy = y0 - 1 + rr, xx = col - 1;
            float v = 0.f;
            if (yy >= 0 && yy < 32 && xx >= 0 && xx < 32)
                v = src[(b * CINT + c0 + ci) * LL + yy * 32 + xx];
            xs[ci][rr][col] = v;
        }
        __syncthreads();

        for (int ci = 0; ci < CCH; ci++) {
            unsigned long long x2[4][3];
#pragma unroll
            for (int rr = 0; rr < 4; rr++)
#pragma unroll
                for (int c = 0; c < 3; c++) {
                    float v = xs[ci][rr][x + c];
                    x2[rr][c] = pk2(v, v);
                }
            const float* wp = &ws[ci * 144 + og * 4];
#pragma unroll
            for (int k = 0; k < 9; k++) {
                const int ky = k / 3, c = k - ky * 3;
                ulonglong2 wA = *(const ulonglong2*)(wp + k * 16);
                acc[0][0] = fma2(wA.x, x2[ky][c],     acc[0][0]);
                acc[0][1] = fma2(wA.x, x2[ky + 1][c], acc[0][1]);
                acc[1][0] = fma2(wA.y, x2[ky][c],     acc[1][0]);
                acc[1][1] = fma2(wA.y, x2[ky + 1][c], acc[1][1]);
            }
        }
    }

#pragma unroll
    for (int p = 0; p < 2; p++) {
        const int oc0 = ocbase + og * 4 + 2 * p;
        float b0 = bias[oc0], b1 = bias[oc0 + 1];
#pragma unroll
        for (int r = 0; r < 2; r++) {
            float a, bb;
            upk2(acc[p][r], a, bb);
            out[(b * 128 + oc_off + oc0) * LL + (y0 + r) * 32 + x]     = a + b0;
            out[(b * 128 + oc_off + oc0 + 1) * LL + (y0 + r) * 32 + x] = bb + b1;
        }
    }
}

// ---------------------------------------------------------------------------
// Launch
// ---------------------------------------------------------------------------
extern "C" void kernel_launch(void* const* d_in, const int* in_sizes, int n_in,
                              void* d_out, int out_size)
{
    const float* x         = (const float*)d_in[0];
    const float* w_general = (const float*)d_in[1];
    const float* b_general = (const float*)d_in[2];
    const float* w_qkv     = (const float*)d_in[3];
    const float* b_qkv     = (const float*)d_in[4];
    const float* w_out     = (const float*)d_in[5];
    const float* b_out     = (const float*)d_in[6];
    const float* krh       = (const float*)d_in[7];
    const float* krw       = (const float*)d_in[8];
    float* out = (float*)d_out;

    static cudaStream_t s2 = nullptr;
    static cudaEvent_t ev_fork = nullptr, ev_join = nullptr;
    static float *p_wtg = nullptr, *p_wto = nullptr, *p_wqt = nullptr;
    if (s2 == nullptr) {
        cudaStreamCreateWithFlags(&s2, cudaStreamNonBlocking);
        cudaEventCreateWithFlags(&ev_fork, cudaEventDisableTiming);
        cudaEventCreateWithFlags(&ev_join, cudaEventDisableTiming);
        cudaFuncSetAttribute(attn_kernel,
                             cudaFuncAttributeMaxDynamicSharedMemorySize, 51200);
        cudaGetSymbolAddress((void**)&p_wtg, g_wtg);
        cudaGetSymbolAddress((void**)&p_wto, g_wto);
        cudaGetSymbolAddress((void**)&p_wqt, g_wqt);
    }

    // weight transposes (main stream, before fork)
    transpose_w_kernel<<<288, 256>>>(w_general, p_wtg, 1152, 64);
    transpose_w_kernel<<<144, 256>>>(w_out, p_wto, 576, 64);
    transpose_w_kernel<<<96, 256>>>(w_qkv, p_wqt, 128, 192);

    cudaEventRecord(ev_fork, 0);
    cudaStreamWaitEvent(s2, ev_fork, 0);
    conv3x3_kernel<128, false><<<dim3(16, NB, 4), 128, 0, s2>>>(x, p_wtg, b_general, out, 0);
    cudaEventRecord(ev_join, s2);

    qkv_kernel<<<dim3(64, NB), 192>>>(x, b_qkv);
    rel_kernel<<<dim3(32, NB * NHH), 1024>>>(krh, krw);
    attn_kernel<<<dim3(8, NB * NHH), 128, 51200>>>();
    combine_kernel<<<64, 256>>>();
    conv3x3_kernel<64, true><<<dim3(16, NB, 4), 128>>>(nullptr, p_wto, b_out, out, 64);

    cudaStreamWaitEvent(0, ev_join, 0);
}